// round 7
// baseline (speedup 1.0000x reference)
#include <cuda_runtime.h>

// KDE: density[n] = (1/M) * sum_m exp( (2*dot(x_n,d_m) - |x_n|^2 - |d_m|^2) * C )
// C = 0.5/sqrt(2*pi), h = 1.
//
// Strategy: fp32 SIMT GEMM (FMA-pipe bound), fused exp epilogue (MUFU pipe,
// free), deterministic fixed-order reduction via __device__ partials buffer.

#define D     128     // feature dim (fixed by problem)
#define BM    64      // rows (x) per CTA tile
#define BN    64      // cols (data) per CTA tile
#define BK    64      // k-chunk
#define PITCH 68      // smem row pitch in floats: 68*4=272B = 17*16B -> float4-aligned rows
#define MAXROWS 8192
#define MAXCT   128   // max column tiles (M/BN)

__device__ float g_xn[MAXROWS];              // |x_n|^2
__device__ float g_dn[MAXROWS];              // |d_m|^2
__device__ float g_part[MAXCT * MAXROWS];    // partial sums per (col-tile, row)

// ---------------------------------------------------------------------------
// Kernel 1: row norms of x and data
// ---------------------------------------------------------------------------
__global__ void norms_kernel(const float* __restrict__ x,
                             const float* __restrict__ dat,
                             int N, int M) {
    int r = blockIdx.x * blockDim.x + threadIdx.x;
    if (r < N) {
        const float4* p = (const float4*)(x + (size_t)r * D);
        float s = 0.f;
        #pragma unroll
        for (int i = 0; i < D / 4; i++) {
            float4 v = p[i];
            s += v.x * v.x + v.y * v.y + v.z * v.z + v.w * v.w;
        }
        g_xn[r] = s;
    }
    if (r < M) {
        const float4* p = (const float4*)(dat + (size_t)r * D);
        float s = 0.f;
        #pragma unroll
        for (int i = 0; i < D / 4; i++) {
            float4 v = p[i];
            s += v.x * v.x + v.y * v.y + v.z * v.z + v.w * v.w;
        }
        g_dn[r] = s;
    }
}

// ---------------------------------------------------------------------------
// Kernel 2: tiled GEMM (dot products) + fused exp + per-tile row sums.
// Grid: (M/BN, N/BM). 256 threads = 16x16, each thread owns a 4x4 micro-tile.
// ---------------------------------------------------------------------------
__global__ __launch_bounds__(256)
void kde_main(const float* __restrict__ x,
              const float* __restrict__ dat,
              int N, int M) {
    // Transposed tiles: [k][n], pitch 68 floats keeps float4 alignment per row
    // and breaks the power-of-two bank pattern on the transposed fill stores.
    __shared__ __align__(16) float xs[BK][PITCH];
    __shared__ __align__(16) float ds[BK][PITCH];

    const int tid = threadIdx.x;
    const int tx  = tid & 15;          // 0..15 -> column group
    const int ty  = tid >> 4;          // 0..15 -> row group
    const int rowBase = blockIdx.y * BM;
    const int colBase = blockIdx.x * BN;

    float acc[4][4];
    #pragma unroll
    for (int i = 0; i < 4; i++)
        #pragma unroll
        for (int j = 0; j < 4; j++)
            acc[i][j] = 0.f;

    // Fill mapping: thread -> (n = tid/4, q = tid%4); each thread moves
    // 4 float4 per tile per chunk. Global reads are 64B-contiguous per row.
    const int fn = tid >> 2;           // 0..63
    const int fq = tid & 3;            // 0..3

    for (int kb = 0; kb < D; kb += BK) {
        const float* xrow = x   + (size_t)(rowBase + fn) * D + kb;
        const float* drow = dat + (size_t)(colBase + fn) * D + kb;
        #pragma unroll
        for (int i = 0; i < 4; i++) {
            int k4 = fq + 4 * i;                      // float4 index 0..15
            float4 vx = *(const float4*)(xrow + k4 * 4);
            float4 vd = *(const float4*)(drow + k4 * 4);
            int k = k4 * 4;
            xs[k + 0][fn] = vx.x; xs[k + 1][fn] = vx.y;
            xs[k + 2][fn] = vx.z; xs[k + 3][fn] = vx.w;
            ds[k + 0][fn] = vd.x; ds[k + 1][fn] = vd.y;
            ds[k + 2][fn] = vd.z; ds[k + 3][fn] = vd.w;
        }
        __syncthreads();

        // Inner loop: 2x LDS.128 + 16 FFMA per k. Unroll 16 keeps the body
        // inside L0 I$ while batching loads for latency hiding.
        #pragma unroll 16
        for (int k = 0; k < BK; k++) {
            float4 a4 = *(const float4*)&xs[k][ty * 4];
            float4 b4 = *(const float4*)&ds[k][tx * 4];
            float a[4] = {a4.x, a4.y, a4.z, a4.w};
            float b[4] = {b4.x, b4.y, b4.z, b4.w};
            #pragma unroll
            for (int i = 0; i < 4; i++)
                #pragma unroll
                for (int j = 0; j < 4; j++)
                    acc[i][j] = fmaf(a[i], b[j], acc[i][j]);
        }
        __syncthreads();
    }

    // Epilogue: exponent = (2*dot - |x|^2 - |d|^2) * C, sum exp over the
    // tile's M-columns, reduce across the 16 tx lanes (half-warp), write
    // one partial per (col-tile, row). No atomics -> deterministic.
    const float Cc = 0.19947114020071633897f;  // 0.5 / sqrt(2*pi)
    float xn[4], dn[4];
    #pragma unroll
    for (int i = 0; i < 4; i++) xn[i] = g_xn[rowBase + ty * 4 + i];
    #pragma unroll
    for (int j = 0; j < 4; j++) dn[j] = g_dn[colBase + tx * 4 + j];

    #pragma unroll
    for (int i = 0; i < 4; i++) {
        float s = 0.f;
        #pragma unroll
        for (int j = 0; j < 4; j++) {
            float e = (2.0f * acc[i][j] - xn[i] - dn[j]) * Cc;
            s += __expf(e);
        }
        // reduce across tx: lanes 0..15 and 16..31 are independent ty rows
        s += __shfl_down_sync(0xFFFFFFFFu, s, 8, 16);
        s += __shfl_down_sync(0xFFFFFFFFu, s, 4, 16);
        s += __shfl_down_sync(0xFFFFFFFFu, s, 2, 16);
        s += __shfl_down_sync(0xFFFFFFFFu, s, 1, 16);
        if (tx == 0)
            g_part[(size_t)blockIdx.x * N + rowBase + ty * 4 + i] = s;
    }
}

// ---------------------------------------------------------------------------
// Kernel 3: fixed-order reduction over column tiles -> output density.
// Also the only writer of d_out (fully initializes it; harness poisons 0xAA).
// ---------------------------------------------------------------------------
__global__ void reduce_kernel(float* __restrict__ out, int N, int M, int nct) {
    int r = blockIdx.x * blockDim.x + threadIdx.x;
    if (r >= N) return;
    float s = 0.f;
    for (int t = 0; t < nct; t++)
        s += g_part[(size_t)t * N + r];
    out[r] = s * (1.0f / (float)M);
}

// ---------------------------------------------------------------------------
extern "C" void kernel_launch(void* const* d_in, const int* in_sizes, int n_in,
                              void* d_out, int out_size) {
    const float* x   = (const float*)d_in[0];
    const float* dat = (const float*)d_in[1];
    float* out = (float*)d_out;

    int N = in_sizes[0] / D;   // 8192
    int M = in_sizes[1] / D;   // 8192
    int R = (N > M) ? N : M;

    norms_kernel<<<(R + 255) / 256, 256>>>(x, dat, N, M);

    dim3 grid(M / BN, N / BM);  // (128, 128) tiles
    kde_main<<<grid, 256>>>(x, dat, N, M);

    reduce_kernel<<<(N + 255) / 256, 256>>>(out, N, M, M / BN);
}

// round 9
// speedup vs baseline: 2.5698x; 2.5698x over previous
#include <cuda_runtime.h>
#include <cuda_bf16.h>
#include <cstdint>

// KDE via mma.sync bf16 tensor-core GEMM (3xBF16 split folded into K=384),
// cp.async double-buffered pipeline, fused exp epilogue, deterministic
// fixed-order reduction. All instructions are sm_80-baseline (the harness
// targets plain compute_103, so sm_10Xa features like tcgen05 are rejected).
//
// density[n] = (1/M) * sum_m exp( (2*dot(x_n,d_m) - |x_n|^2 - |d_m|^2) * C )

#define DDIM   128
#define KAUG   384            // [hi|hi|lo] x [hi|lo|hi]
#define BM     128            // x rows per CTA
#define BN     256            // data rows per CTA
#define BKB    64             // bf16 K per stage
#define NST    (KAUG / BKB)   // 6
#define PITCHB 144            // smem row pitch bytes (72 bf16) -> ldmatrix conflict-free
#define MAXROWS 8192
#define MAXCHUNK 128

#define CC  0.19947114020071633897f    // 0.5 / sqrt(2*pi)

__device__ __align__(256) __nv_bfloat16 g_xa[MAXROWS * KAUG];  // 6.3 MB
__device__ __align__(256) __nv_bfloat16 g_da[MAXROWS * KAUG];
__device__ float g_xn[MAXROWS];
__device__ float g_dn[MAXROWS];
__device__ float g_part[MAXCHUNK * MAXROWS];

// ---------------------------------------------------------------------------
__device__ __forceinline__ uint32_t smem_u32(const void* p) {
    uint32_t a;
    asm("{ .reg .u64 t; cvta.to.shared.u64 t, %1; cvt.u32.u64 %0, t; }"
        : "=r"(a) : "l"(p));
    return a;
}
__device__ __forceinline__ void cp16(uint32_t dst, const void* src) {
    asm volatile("cp.async.cg.shared.global [%0], [%1], 16;"
                 :: "r"(dst), "l"(src) : "memory");
}
__device__ __forceinline__ void ldmx4(uint32_t* r, uint32_t addr) {
    asm volatile("ldmatrix.sync.aligned.m8n8.x4.shared.b16 {%0,%1,%2,%3}, [%4];"
                 : "=r"(r[0]), "=r"(r[1]), "=r"(r[2]), "=r"(r[3]) : "r"(addr));
}
__device__ __forceinline__ void mma_bf16(float* c, const uint32_t* a,
                                         uint32_t b0, uint32_t b1) {
    asm volatile(
        "mma.sync.aligned.m16n8k16.row.col.f32.bf16.bf16.f32 "
        "{%0,%1,%2,%3}, {%4,%5,%6,%7}, {%8,%9}, {%0,%1,%2,%3};"
        : "+f"(c[0]), "+f"(c[1]), "+f"(c[2]), "+f"(c[3])
        : "r"(a[0]), "r"(a[1]), "r"(a[2]), "r"(a[3]), "r"(b0), "r"(b1));
}
__device__ __forceinline__ uint32_t packbf2(float a, float b) {
    __nv_bfloat162 p = __floats2bfloat162_rn(a, b);
    return *reinterpret_cast<uint32_t*>(&p);
}

// ---------------------------------------------------------------------------
// Kernel 1: bf16 hi/lo split into augmented matrices + fp32 row norms.
// One warp per row; lane handles one float4.
// ---------------------------------------------------------------------------
__global__ __launch_bounds__(256)
void prep_kernel(const float* __restrict__ x, const float* __restrict__ dat,
                 int N, int M) {
    int w = (blockIdx.x * blockDim.x + threadIdx.x) >> 5;
    int lane = threadIdx.x & 31;
    int R = (N > M) ? N : M;
    if (w >= R) return;

    #pragma unroll
    for (int which = 0; which < 2; which++) {
        const float* src = which ? dat : x;
        if ((which ? M : N) <= w) continue;
        float4 v = ((const float4*)(src + (size_t)w * DDIM))[lane];
        float hx = __bfloat162float(__float2bfloat16_rn(v.x));
        float hy = __bfloat162float(__float2bfloat16_rn(v.y));
        float hz = __bfloat162float(__float2bfloat16_rn(v.z));
        float hw = __bfloat162float(__float2bfloat16_rn(v.w));
        uint2 hi = make_uint2(packbf2(v.x, v.y), packbf2(v.z, v.w));
        uint2 lo = make_uint2(packbf2(v.x - hx, v.y - hy),
                              packbf2(v.z - hz, v.w - hw));
        uint2* dst = (uint2*)((which ? g_da : g_xa) + (size_t)w * KAUG) + lane;
        if (which == 0) {            // X: [hi | hi | lo]
            dst[0] = hi; dst[32] = hi; dst[64] = lo;
        } else {                     // D: [hi | lo | hi]
            dst[0] = hi; dst[32] = lo; dst[64] = hi;
        }
        float s = v.x * v.x + v.y * v.y + v.z * v.z + v.w * v.w;
        #pragma unroll
        for (int o = 16; o > 0; o >>= 1) s += __shfl_down_sync(0xFFFFFFFFu, s, o);
        if (lane == 0) { if (which) g_dn[w] = s; else g_xn[w] = s; }
    }
}

// ---------------------------------------------------------------------------
// Kernel 2: 128x256 tile per CTA, 512 threads = 16 warps (4 M x 4 N),
// warp tile 32x64. cp.async double-buffered K pipeline, bf16 HMMA,
// fused exp epilogue, per-(chunk,row) partials.
// ---------------------------------------------------------------------------
#define SO_DNS 0
#define SA_BYTES (128 * PITCHB)            // 18432
#define SB_BYTES (256 * PITCHB)            // 36864
#define SO_A   1024
#define SO_B   (SO_A + 2 * SA_BYTES)       // 37888
#define SMEMT  (SO_B + 2 * SB_BYTES)       // 111616 B

__global__ __launch_bounds__(512, 1)
void kde_mma(int N, int M) {
    extern __shared__ char smem[];
    const uint32_t sb = smem_u32(smem);
    const int tid = threadIdx.x, lane = tid & 31, w = tid >> 5;
    const int wm = w >> 2, wn = w & 3;
    const int rowBase = blockIdx.y * BM;
    const int colBase = blockIdx.x * BN;

    if (tid < 256)
        *(float*)(smem + SO_DNS + tid * 4) = -g_dn[colBase + tid] * CC;

    const __nv_bfloat16* Ag = g_xa + (size_t)rowBase * KAUG;
    const __nv_bfloat16* Bg = g_da + (size_t)colBase * KAUG;

    float acc[2][8][4];
    #pragma unroll
    for (int i = 0; i < 2; i++)
        #pragma unroll
        for (int j = 0; j < 8; j++)
            #pragma unroll
            for (int c = 0; c < 4; c++) acc[i][j][c] = 0.f;

    // ldmatrix lane address bases (buffer 0)
    const int bq = lane >> 3, rr = lane & 7;
    const uint32_t aAddr0 = sb + SO_A +
        (uint32_t)((wm * 32 + (bq & 1) * 8 + rr) * PITCHB) + (uint32_t)((lane >> 4) * 16);
    const uint32_t bAddr0 = sb + SO_B +
        (uint32_t)((wn * 64 + (lane >> 4) * 8 + rr) * PITCHB) + (uint32_t)((bq & 1) * 16);

    // cp.async stage issue: A = 1024 x16B (2/thread), B = 2048 x16B (4/thread)
    auto issue = [&](int s) {
        const int kb = s * BKB;                    // bf16 offset within row
        const uint32_t ab = sb + SO_A + (s & 1) * SA_BYTES;
        const uint32_t bb = sb + SO_B + (s & 1) * SB_BYTES;
        #pragma unroll
        for (int i = 0; i < 2; i++) {
            int f = tid + i * 512, r = f >> 3, q = f & 7;
            cp16(ab + r * PITCHB + q * 16, Ag + (size_t)r * KAUG + kb + q * 8);
        }
        #pragma unroll
        for (int i = 0; i < 4; i++) {
            int f = tid + i * 512, r = f >> 3, q = f & 7;
            cp16(bb + r * PITCHB + q * 16, Bg + (size_t)r * KAUG + kb + q * 8);
        }
        asm volatile("cp.async.commit_group;" ::: "memory");
    };

    issue(0);
    for (int s = 0; s < NST; s++) {
        if (s + 1 < NST) {
            issue(s + 1);
            asm volatile("cp.async.wait_group 1;" ::: "memory");
        } else {
            asm volatile("cp.async.wait_group 0;" ::: "memory");
        }
        __syncthreads();

        const uint32_t ab = aAddr0 + (s & 1) * SA_BYTES;
        const uint32_t bb = bAddr0 + (s & 1) * SB_BYTES;
        #pragma unroll
        for (int k4 = 0; k4 < BKB / 16; k4++) {      // 4 k16 steps
            uint32_t a0[4], a1[4];
            ldmx4(a0, ab + k4 * 32);                 // m rows +0..15
            ldmx4(a1, ab + 16 * PITCHB + k4 * 32);   // m rows +16..31
            #pragma unroll
            for (int jj = 0; jj < 4; jj++) {         // 16 n each
                uint32_t b[4];
                ldmx4(b, bb + jj * 16 * PITCHB + k4 * 32);
                mma_bf16(acc[0][2 * jj],     a0, b[0], b[1]);
                mma_bf16(acc[0][2 * jj + 1], a0, b[2], b[3]);
                mma_bf16(acc[1][2 * jj],     a1, b[0], b[1]);
                mma_bf16(acc[1][2 * jj + 1], a1, b[2], b[3]);
            }
        }
        __syncthreads();
    }

    // Epilogue: e = dot*2C - xn*C - dn*C ; sum exp over this warp's 64 cols.
    const float* dnsS = (const float*)(smem + SO_DNS);
    #pragma unroll
    for (int mi = 0; mi < 2; mi++) {
        const int r0 = rowBase + wm * 32 + mi * 16 + (lane >> 2);
        const float xn0 = -g_xn[r0] * CC;
        const float xn1 = -g_xn[r0 + 8] * CC;
        float s0 = 0.f, s1 = 0.f;
        #pragma unroll
        for (int jn = 0; jn < 8; jn++) {
            const int cb = wn * 64 + jn * 8 + 2 * (lane & 3);
            const float d0 = dnsS[cb], d1 = dnsS[cb + 1];
            s0 += __expf(fmaf(acc[mi][jn][0], 2.f * CC, xn0 + d0));
            s0 += __expf(fmaf(acc[mi][jn][1], 2.f * CC, xn0 + d1));
            s1 += __expf(fmaf(acc[mi][jn][2], 2.f * CC, xn1 + d0));
            s1 += __expf(fmaf(acc[mi][jn][3], 2.f * CC, xn1 + d1));
        }
        // reduce across the 4 lanes sharing a row (lane&3)
        s0 += __shfl_xor_sync(0xFFFFFFFFu, s0, 1);
        s0 += __shfl_xor_sync(0xFFFFFFFFu, s0, 2);
        s1 += __shfl_xor_sync(0xFFFFFFFFu, s1, 1);
        s1 += __shfl_xor_sync(0xFFFFFFFFu, s1, 2);
        if ((lane & 3) == 0) {
            const size_t chunk = blockIdx.x * 4 + wn;   // 128 chunks total
            g_part[chunk * N + r0]     = s0;
            g_part[chunk * N + r0 + 8] = s1;
        }
    }
}

// ---------------------------------------------------------------------------
// Kernel 3: fixed-order reduction over 128 column chunks -> density.
// ---------------------------------------------------------------------------
__global__ void reduce_kernel(float* __restrict__ out, int N, int M, int nchunk) {
    int r = blockIdx.x * blockDim.x + threadIdx.x;
    if (r >= N) return;
    float s = 0.f;
    for (int t = 0; t < nchunk; t++) s += g_part[(size_t)t * N + r];
    out[r] = s * (1.0f / (float)M);
}

// ---------------------------------------------------------------------------
extern "C" void kernel_launch(void* const* d_in, const int* in_sizes, int n_in,
                              void* d_out, int out_size) {
    const float* x   = (const float*)d_in[0];
    const float* dat = (const float*)d_in[1];
    float* out = (float*)d_out;

    int N = in_sizes[0] / DDIM;   // 8192
    int M = in_sizes[1] / DDIM;   // 8192
    int R = (N > M) ? N : M;

    cudaFuncSetAttribute(kde_mma, cudaFuncAttributeMaxDynamicSharedMemorySize,
                         SMEMT);

    prep_kernel<<<(R * 32 + 255) / 256, 256>>>(x, dat, N, M);

    dim3 grid(M / BN, N / BM);    // (32, 64) = 2048 CTAs
    kde_mma<<<grid, 512, SMEMT>>>(N, M);

    reduce_kernel<<<(N + 255) / 256, 256>>>(out, N, M, M / 64);
}

// round 11
// speedup vs baseline: 2.6356x; 1.0256x over previous
#include <cuda_runtime.h>
#include <cuda_bf16.h>
#include <cstdint>

// KDE via mma.sync bf16 tensor-core GEMM (3xBF16 split folded into K=384),
// triple-buffered cp.async pipeline (ONE barrier per K-stage), fused exp
// epilogue, deterministic fixed-order reduction.
//
// density[n] = (1/M) * sum_m exp( (2*dot(x_n,d_m) - |x_n|^2 - |d_m|^2) * C )

#define DDIM   128
#define KAUG   384            // [hi|hi|lo] x [hi|lo|hi]
#define BM     128            // x rows per CTA
#define BN     256            // data rows per CTA
#define BKB    64             // bf16 K per stage
#define NST    (KAUG / BKB)   // 6
#define PITCHB 144            // smem row pitch bytes (72 bf16)
#define MAXROWS 8192
#define MAXCHUNK 128

#define CC  0.19947114020071633897f    // 0.5 / sqrt(2*pi)

__device__ __align__(256) __nv_bfloat16 g_xa[MAXROWS * KAUG];  // 6.3 MB
__device__ __align__(256) __nv_bfloat16 g_da[MAXROWS * KAUG];
__device__ float g_xn[MAXROWS];
__device__ float g_dn[MAXROWS];
__device__ float g_part[MAXCHUNK * MAXROWS];

// ---------------------------------------------------------------------------
__device__ __forceinline__ uint32_t smem_u32(const void* p) {
    uint32_t a;
    asm("{ .reg .u64 t; cvta.to.shared.u64 t, %1; cvt.u32.u64 %0, t; }"
        : "=r"(a) : "l"(p));
    return a;
}
__device__ __forceinline__ void cp16(uint32_t dst, const void* src) {
    asm volatile("cp.async.cg.shared.global [%0], [%1], 16;"
                 :: "r"(dst), "l"(src) : "memory");
}
__device__ __forceinline__ void ldmx4(uint32_t* r, uint32_t addr) {
    asm volatile("ldmatrix.sync.aligned.m8n8.x4.shared.b16 {%0,%1,%2,%3}, [%4];"
                 : "=r"(r[0]), "=r"(r[1]), "=r"(r[2]), "=r"(r[3]) : "r"(addr));
}
__device__ __forceinline__ void mma_bf16(float* c, const uint32_t* a,
                                         uint32_t b0, uint32_t b1) {
    asm volatile(
        "mma.sync.aligned.m16n8k16.row.col.f32.bf16.bf16.f32 "
        "{%0,%1,%2,%3}, {%4,%5,%6,%7}, {%8,%9}, {%0,%1,%2,%3};"
        : "+f"(c[0]), "+f"(c[1]), "+f"(c[2]), "+f"(c[3])
        : "r"(a[0]), "r"(a[1]), "r"(a[2]), "r"(a[3]), "r"(b0), "r"(b1));
}
__device__ __forceinline__ uint32_t packbf2(float a, float b) {
    __nv_bfloat162 p = __floats2bfloat162_rn(a, b);
    return *reinterpret_cast<uint32_t*>(&p);
}

// ---------------------------------------------------------------------------
// Kernel 1: bf16 hi/lo split into augmented matrices + fp32 row norms.
// ---------------------------------------------------------------------------
__global__ __launch_bounds__(256)
void prep_kernel(const float* __restrict__ x, const float* __restrict__ dat,
                 int N, int M) {
    int w = (blockIdx.x * blockDim.x + threadIdx.x) >> 5;
    int lane = threadIdx.x & 31;
    int R = (N > M) ? N : M;
    if (w >= R) return;

    #pragma unroll
    for (int which = 0; which < 2; which++) {
        const float* src = which ? dat : x;
        if ((which ? M : N) <= w) continue;
        float4 v = ((const float4*)(src + (size_t)w * DDIM))[lane];
        float hx = __bfloat162float(__float2bfloat16_rn(v.x));
        float hy = __bfloat162float(__float2bfloat16_rn(v.y));
        float hz = __bfloat162float(__float2bfloat16_rn(v.z));
        float hw = __bfloat162float(__float2bfloat16_rn(v.w));
        uint2 hi = make_uint2(packbf2(v.x, v.y), packbf2(v.z, v.w));
        uint2 lo = make_uint2(packbf2(v.x - hx, v.y - hy),
                              packbf2(v.z - hz, v.w - hw));
        uint2* dst = (uint2*)((which ? g_da : g_xa) + (size_t)w * KAUG) + lane;
        if (which == 0) {            // X: [hi | hi | lo]
            dst[0] = hi; dst[32] = hi; dst[64] = lo;
        } else {                     // D: [hi | lo | hi]
            dst[0] = hi; dst[32] = lo; dst[64] = hi;
        }
        float s = v.x * v.x + v.y * v.y + v.z * v.z + v.w * v.w;
        #pragma unroll
        for (int o = 16; o > 0; o >>= 1) s += __shfl_down_sync(0xFFFFFFFFu, s, o);
        if (lane == 0) { if (which) g_dn[w] = s; else g_xn[w] = s; }
    }
}

// ---------------------------------------------------------------------------
// Kernel 2: 128x256 tile per CTA, 512 threads = 16 warps (4 M x 4 N),
// warp tile 32x64. Triple-buffered cp.async (depth 2), ONE sync per stage.
// ---------------------------------------------------------------------------
#define SO_DNS 0
#define SA_BYTES (128 * PITCHB)            // 18432
#define SB_BYTES (256 * PITCHB)            // 36864
#define SO_A   1024
#define SO_B   (SO_A + 3 * SA_BYTES)       // 56320
#define SMEMT  (SO_B + 3 * SB_BYTES)       // 166912 B (fits 228KB, 1 CTA/SM)

__global__ __launch_bounds__(512, 1)
void kde_mma(int N, int M) {
    extern __shared__ char smem[];
    const uint32_t sb = smem_u32(smem);
    const int tid = threadIdx.x, lane = tid & 31, w = tid >> 5;
    const int wm = w >> 2, wn = w & 3;
    const int rowBase = blockIdx.y * BM;
    const int colBase = blockIdx.x * BN;

    if (tid < 256)
        *(float*)(smem + SO_DNS + tid * 4) = -g_dn[colBase + tid] * CC;

    const __nv_bfloat16* Ag = g_xa + (size_t)rowBase * KAUG;
    const __nv_bfloat16* Bg = g_da + (size_t)colBase * KAUG;

    float acc[2][8][4];
    #pragma unroll
    for (int i = 0; i < 2; i++)
        #pragma unroll
        for (int j = 0; j < 8; j++)
            #pragma unroll
            for (int c = 0; c < 4; c++) acc[i][j][c] = 0.f;

    // ldmatrix lane address bases (buffer 0)
    const int bq = lane >> 3, rr = lane & 7;
    const uint32_t aAddr0 = sb + SO_A +
        (uint32_t)((wm * 32 + (bq & 1) * 8 + rr) * PITCHB) + (uint32_t)((lane >> 4) * 16);
    const uint32_t bAddr0 = sb + SO_B +
        (uint32_t)((wn * 64 + (lane >> 4) * 8 + rr) * PITCHB) + (uint32_t)((bq & 1) * 16);

    // cp.async stage issue: A = 1024 x16B (2/thread), B = 2048 x16B (4/thread)
    auto issue = [&](int s) {
        const int kb = s * BKB;
        const int buf = s % 3;
        const uint32_t ab = sb + SO_A + buf * SA_BYTES;
        const uint32_t bb = sb + SO_B + buf * SB_BYTES;
        #pragma unroll
        for (int i = 0; i < 2; i++) {
            int f = tid + i * 512, r = f >> 3, q = f & 7;
            cp16(ab + r * PITCHB + q * 16, Ag + (size_t)r * KAUG + kb + q * 8);
        }
        #pragma unroll
        for (int i = 0; i < 4; i++) {
            int f = tid + i * 512, r = f >> 3, q = f & 7;
            cp16(bb + r * PITCHB + q * 16, Bg + (size_t)r * KAUG + kb + q * 8);
        }
        asm volatile("cp.async.commit_group;" ::: "memory");
    };

    issue(0);
    issue(1);
    for (int s = 0; s < NST; s++) {
        // Stage s's group must be complete; allow the (s+1) group to stay
        // in flight. One barrier both publishes buffer s and proves all
        // warps are done reading buffer (s+2)%3 (read in iteration s-1).
        if (s < NST - 1)
            asm volatile("cp.async.wait_group 1;" ::: "memory");
        else
            asm volatile("cp.async.wait_group 0;" ::: "memory");
        __syncthreads();
        if (s + 2 < NST) issue(s + 2);   // overlaps this stage's compute

        const int buf = s % 3;
        const uint32_t ab = aAddr0 + buf * SA_BYTES;
        const uint32_t bb = bAddr0 + buf * SB_BYTES;
        #pragma unroll
        for (int k4 = 0; k4 < BKB / 16; k4++) {      // 4 k16 steps
            uint32_t a0[4], a1[4];
            ldmx4(a0, ab + k4 * 32);                 // m rows +0..15
            ldmx4(a1, ab + 16 * PITCHB + k4 * 32);   // m rows +16..31
            #pragma unroll
            for (int jj = 0; jj < 4; jj++) {         // 16 n each
                uint32_t b[4];
                ldmx4(b, bb + jj * 16 * PITCHB + k4 * 32);
                mma_bf16(acc[0][2 * jj],     a0, b[0], b[1]);
                mma_bf16(acc[0][2 * jj + 1], a0, b[2], b[3]);
                mma_bf16(acc[1][2 * jj],     a1, b[0], b[1]);
                mma_bf16(acc[1][2 * jj + 1], a1, b[2], b[3]);
            }
        }
    }

    // Epilogue: e = dot*2C - xn*C - dn*C ; sum exp over this warp's 64 cols.
    // (dns staged pre-loop; visible since the first __syncthreads.)
    const float* dnsS = (const float*)(smem + SO_DNS);
    #pragma unroll
    for (int mi = 0; mi < 2; mi++) {
        const int r0 = rowBase + wm * 32 + mi * 16 + (lane >> 2);
        const float xn0 = -g_xn[r0] * CC;
        const float xn1 = -g_xn[r0 + 8] * CC;
        float s0 = 0.f, s1 = 0.f;
        #pragma unroll
        for (int jn = 0; jn < 8; jn++) {
            const int cb = wn * 64 + jn * 8 + 2 * (lane & 3);
            const float d0 = dnsS[cb], d1 = dnsS[cb + 1];
            s0 += __expf(fmaf(acc[mi][jn][0], 2.f * CC, xn0 + d0));
            s0 += __expf(fmaf(acc[mi][jn][1], 2.f * CC, xn0 + d1));
            s1 += __expf(fmaf(acc[mi][jn][2], 2.f * CC, xn1 + d0));
            s1 += __expf(fmaf(acc[mi][jn][3], 2.f * CC, xn1 + d1));
        }
        s0 += __shfl_xor_sync(0xFFFFFFFFu, s0, 1);
        s0 += __shfl_xor_sync(0xFFFFFFFFu, s0, 2);
        s1 += __shfl_xor_sync(0xFFFFFFFFu, s1, 1);
        s1 += __shfl_xor_sync(0xFFFFFFFFu, s1, 2);
        if ((lane & 3) == 0) {
            const size_t chunk = blockIdx.x * 4 + wn;   // 128 chunks total
            g_part[chunk * N + r0]     = s0;
            g_part[chunk * N + r0 + 8] = s1;
        }
    }
}

// ---------------------------------------------------------------------------
// Kernel 3: fixed-order reduction over 128 column chunks -> density.
// ---------------------------------------------------------------------------
__global__ void reduce_kernel(float* __restrict__ out, int N, int M, int nchunk) {
    int r = blockIdx.x * blockDim.x + threadIdx.x;
    if (r >= N) return;
    float s = 0.f;
    for (int t = 0; t < nchunk; t++) s += g_part[(size_t)t * N + r];
    out[r] = s * (1.0f / (float)M);
}

// ---------------------------------------------------------------------------
extern "C" void kernel_launch(void* const* d_in, const int* in_sizes, int n_in,
                              void* d_out, int out_size) {
    const float* x   = (const float*)d_in[0];
    const float* dat = (const float*)d_in[1];
    float* out = (float*)d_out;

    int N = in_sizes[0] / DDIM;   // 8192
    int M = in_sizes[1] / DDIM;   // 8192
    int R = (N > M) ? N : M;

    cudaFuncSetAttribute(kde_mma, cudaFuncAttributeMaxDynamicSharedMemorySize,
                         SMEMT);

    prep_kernel<<<(R * 32 + 255) / 256, 256>>>(x, dat, N, M);

    dim3 grid(M / BN, N / BM);    // (32, 64) = 2048 CTAs
    kde_mma<<<grid, 512, SMEMT>>>(N, M);

    reduce_kernel<<<(N + 255) / 256, 256>>>(out, N, M, M / 64);
}